// round 3
// baseline (speedup 1.0000x reference)
#include <cuda_runtime.h>
#include <cuda_bf16.h>
#include <stdint.h>

// Problem shape (fixed by setup_inputs)
#define DD   512
#define BQ   1024
#define MKEY 60000
#define TOPK 50
#define NCLS 10
#define CHKSTR 1880      // per-row chunk-max stride (>= ceil(M/32))

// ---------------- device scratch (static, allocation-free) ----------------
__device__ alignas(128) __nv_bfloat16 g_xhi[(size_t)BQ * DD];
__device__ alignas(128) __nv_bfloat16 g_xlo[(size_t)BQ * DD];
__device__ alignas(128) __nv_bfloat16 g_khi[(size_t)MKEY * DD];
__device__ alignas(128) __nv_bfloat16 g_klo[(size_t)MKEY * DD];
__device__ float         g_scores[(size_t)BQ * MKEY];     // 245.8 MB
__device__ unsigned      g_cmax[(size_t)BQ * CHKSTR];     // 7.7 MB mono chunk maxima
__device__ int           g_val_is64;

// ---------------- PTX helpers ----------------
__device__ __forceinline__ uint32_t s2u(const void* p) {
    return (uint32_t)__cvta_generic_to_shared(p);
}
__device__ __forceinline__ void cpa16(uint32_t dst, const void* src, int sz) {
    asm volatile("cp.async.cg.shared.global [%0], [%1], 16, %2;\n"
                 :: "r"(dst), "l"(src), "r"(sz));
}
__device__ __forceinline__ void cp_commit() {
    asm volatile("cp.async.commit_group;\n");
}
template <int N>
__device__ __forceinline__ void cp_wait() {
    asm volatile("cp.async.wait_group %0;\n" :: "n"(N));
}
__device__ __forceinline__ void ldmx4(uint32_t* r, uint32_t a) {
    asm volatile("ldmatrix.sync.aligned.m8n8.x4.shared.b16 {%0,%1,%2,%3}, [%4];\n"
                 : "=r"(r[0]), "=r"(r[1]), "=r"(r[2]), "=r"(r[3]) : "r"(a));
}
__device__ __forceinline__ void mma_bf16(float* c, const uint32_t* a, const uint32_t* b) {
    asm volatile(
        "mma.sync.aligned.m16n8k16.row.col.f32.bf16.bf16.f32 "
        "{%0,%1,%2,%3},{%4,%5,%6,%7},{%8,%9},{%0,%1,%2,%3};\n"
        : "+f"(c[0]), "+f"(c[1]), "+f"(c[2]), "+f"(c[3])
        : "r"(a[0]), "r"(a[1]), "r"(a[2]), "r"(a[3]), "r"(b[0]), "r"(b[1]));
}
__device__ __forceinline__ unsigned mono_u32(float v) {
    unsigned u = __float_as_uint(v);
    return (u & 0x80000000u) ? ~u : (u | 0x80000000u);
}

// ---------------- normalize + bf16 split ----------------
__global__ void norm_split_kernel(const float* __restrict__ src, int which) {
    const int row = blockIdx.x;
    const int t   = threadIdx.x;               // 128 threads
    const float* r = src + (size_t)row * DD;

    float v[4];
    float ss = 0.f;
#pragma unroll
    for (int j = 0; j < 4; j++) {
        v[j] = r[t + 128 * j];
        ss += v[j] * v[j];
    }
#pragma unroll
    for (int o = 16; o; o >>= 1) ss += __shfl_xor_sync(0xffffffffu, ss, o);
    __shared__ float ws[4];
    if ((t & 31) == 0) ws[t >> 5] = ss;
    __syncthreads();
    const float tot = ws[0] + ws[1] + ws[2] + ws[3];
    const float inv = 1.0f / fmaxf(sqrtf(tot), 1e-12f);

    __nv_bfloat16* hi = which ? g_khi : g_xhi;
    __nv_bfloat16* lo = which ? g_klo : g_xlo;
#pragma unroll
    for (int j = 0; j < 4; j++) {
        float xn = v[j] * inv;
        __nv_bfloat16 h = __float2bfloat16(xn);
        float rem = xn - __bfloat162float(h);
        size_t o2 = (size_t)row * DD + t + 128 * j;
        hi[o2] = h;
        lo[o2] = __float2bfloat16(rem);
    }
}

// ---------------- values dtype sniffing (jax may demote int64 -> int32) ---
__global__ void detect_values_kernel(const void* vals) {
    const long long* p = (const long long*)vals;
    int ok = 1;
    for (int i = 0; i < 64; i++) {
        long long vv = p[i];
        if (vv < 0 || vv >= NCLS) { ok = 0; break; }
    }
    g_val_is64 = ok;
}

// ---------------- GEMM: scores = xhi*klo + xlo*khi + xhi*khi (K = 3*512) --
// CTA 128x128, 4 warps (2x2), warp tile 64x64, KT=64, 3-stage cp.async for B.
// A fragments loaded directly from global (L1/L2 resident) - no A smem.
#define KT    64
#define PADH  72       // halves per B smem row (64 data + 8 pad) -> 144B stride
#define NSTG  3
#define NTILE 24       // 1536 / 64

__global__ void __launch_bounds__(128) gemm_kernel(int M) {
    extern __shared__ __align__(16) __nv_bfloat16 Bs[];   // [NSTG][128*PADH]

    const int tid  = threadIdx.x;
    const int lane = tid & 31;
    const int w    = tid >> 5;
    const int wm   = w & 1;         // 64-row slab
    const int wn   = w >> 1;        // 64-col slab
    const int bm0  = blockIdx.x * 128;
    const int bn0  = blockIdx.y * 128;

    float acc[4][8][4];
#pragma unroll
    for (int a = 0; a < 4; a++)
#pragma unroll
        for (int b = 0; b < 8; b++)
#pragma unroll
            for (int c = 0; c < 4; c++) acc[a][b][c] = 0.f;

    auto loadB = [&](int t, int stg) {
        const int seg  = t >> 3;                 // 0: klo, 1/2: khi
        const int koff = (t & 7) * 64;
        const __nv_bfloat16* Bsrc = (seg == 0) ? g_klo : g_khi;
        __nv_bfloat16* dst = Bs + (size_t)stg * 128 * PADH;
#pragma unroll
        for (int i = 0; i < 8; i++) {
            const int c = tid + i * 128;         // 1024 16B chunks
            const int r = c >> 3, sub = c & 7;
            const int n = bn0 + r;
            const int ok = (n < M) ? 16 : 0;     // zero-fill OOB keys
            cpa16(s2u(dst + r * PADH + sub * 8),
                  Bsrc + (size_t)((n < M) ? n : 0) * DD + koff + sub * 8, ok);
        }
    };

    loadB(0, 0); cp_commit();
    loadB(1, 1); cp_commit();

    const int arow0 = bm0 + wm * 64 + (lane >> 2);   // lane's base A row

    for (int t = 0; t < NTILE; t++) {
        const int stg  = t % NSTG;
        const int seg  = t >> 3;                 // 0: xhi, 1: xlo, 2: xhi
        const int koff = (t & 7) * 64;
        const __nv_bfloat16* Asrc = (seg == 1) ? g_xlo : g_xhi;
        // lane-resolved base pointer for A fragment loads
        const __nv_bfloat16* ap =
            Asrc + (size_t)arow0 * DD + koff + (lane & 3) * 2;
        const __nv_bfloat16* Bbase = Bs + (size_t)stg * 128 * PADH;

        cp_wait<1>();
        __syncthreads();

        uint32_t afr[2][4][4];
        uint32_t bfr[2][8][2];

        // frag loader for k-substep kh into buffer bb
        auto loadFrags = [&](int kh, int bb) {
#pragma unroll
            for (int mt = 0; mt < 4; mt++) {
                const __nv_bfloat16* p = ap + (size_t)mt * 16 * DD + kh * 16;
                afr[bb][mt][0] = *(const uint32_t*)(p);
                afr[bb][mt][1] = *(const uint32_t*)(p + 8 * DD);
                afr[bb][mt][2] = *(const uint32_t*)(p + 8);
                afr[bb][mt][3] = *(const uint32_t*)(p + 8 * DD + 8);
            }
            const int q = lane >> 3;
#pragma unroll
            for (int np = 0; np < 4; np++) {
                const int rr = wn * 64 + np * 16 + ((q >> 1) << 3) + (lane & 7);
                const int cc = kh * 16 + ((q & 1) << 3);
                uint32_t tmp[4];
                ldmx4(tmp, s2u(Bbase + rr * PADH + cc));
                bfr[bb][np * 2 + 0][0] = tmp[0];
                bfr[bb][np * 2 + 0][1] = tmp[1];
                bfr[bb][np * 2 + 1][0] = tmp[2];
                bfr[bb][np * 2 + 1][1] = tmp[3];
            }
        };

        loadFrags(0, 0);
#pragma unroll
        for (int kh = 0; kh < 4; kh++) {
            const int cur = kh & 1;
            if (kh < 3) loadFrags(kh + 1, cur ^ 1);
#pragma unroll
            for (int mt = 0; mt < 4; mt++)
#pragma unroll
                for (int nt = 0; nt < 8; nt++)
                    mma_bf16(acc[mt][nt], afr[cur][mt], bfr[cur][nt]);
        }

        if (t + 2 < NTILE) loadB(t + 2, (t + 2) % NSTG);
        cp_commit();
    }

    // ---------------- epilogue: scores (float2) + per-32-chunk row maxima --
#pragma unroll
    for (int mt = 0; mt < 4; mt++) {
        const int r0 = bm0 + wm * 64 + mt * 16 + (lane >> 2);
#pragma unroll
        for (int nt = 0; nt < 8; nt++) {
            const int c0 = bn0 + wn * 64 + nt * 8 + (lane & 3) * 2;
            if (c0 < M) {
                float2 v0 = make_float2(acc[mt][nt][0], acc[mt][nt][1]);
                float2 v1 = make_float2(acc[mt][nt][2], acc[mt][nt][3]);
                *(float2*)&g_scores[(size_t)r0 * M + c0]       = v0;
                *(float2*)&g_scores[(size_t)(r0 + 8) * M + c0] = v1;
            }
        }
        // chunk maxima: two 32-col chunks per warp slab
#pragma unroll
        for (int cg = 0; cg < 2; cg++) {
            float m0 = -1e30f, m1 = -1e30f;
#pragma unroll
            for (int j = 0; j < 4; j++) {
                const int nt = cg * 4 + j;
                m0 = fmaxf(m0, fmaxf(acc[mt][nt][0], acc[mt][nt][1]));
                m1 = fmaxf(m1, fmaxf(acc[mt][nt][2], acc[mt][nt][3]));
            }
            m0 = fmaxf(m0, __shfl_xor_sync(0xffffffffu, m0, 1));
            m0 = fmaxf(m0, __shfl_xor_sync(0xffffffffu, m0, 2));
            m1 = fmaxf(m1, __shfl_xor_sync(0xffffffffu, m1, 1));
            m1 = fmaxf(m1, __shfl_xor_sync(0xffffffffu, m1, 2));
            const int cbase = bn0 + wn * 64 + cg * 32;
            if ((lane & 3) == 0 && cbase < M) {
                g_cmax[(size_t)r0 * CHKSTR + (cbase >> 5)]       = mono_u32(m0);
                g_cmax[(size_t)(r0 + 8) * CHKSTR + (cbase >> 5)] = mono_u32(m1);
            }
        }
    }
}

// ---------------- per-row top-k + class vote (chunk-max pruned) -----------
__global__ void __launch_bounds__(256) topk_vote_kernel(
    const void* __restrict__ values_raw, float* __restrict__ out,
    int M, int nchunks) {
    const int b    = blockIdx.x;
    const int tid  = threadIdx.x;
    const int lane = tid & 31;
    const int w    = tid >> 5;

    __shared__ unsigned hist[4096];
    __shared__ unsigned chs[256];
    __shared__ int      sT;
    __shared__ unsigned sNc, sNch;
    __shared__ int      chlist[1024];
    __shared__ unsigned cand_u[2048];
    __shared__ int      cand_i[2048];
    __shared__ float    cand_v[2048];
    __shared__ unsigned long long redK[8];
    __shared__ int      redS[8];
    __shared__ float    cls[NCLS];

    for (int i = tid; i < 4096; i += 256) hist[i] = 0u;
    if (tid < NCLS) cls[tid] = 0.f;
    if (tid == 0) { sNc = 0u; sNch = 0u; }
    __syncthreads();

    const unsigned* cmax = g_cmax + (size_t)b * CHKSTR;

    // phase 1: histogram of chunk maxima (12-bit radix over mono bits)
    for (int i = tid; i < nchunks; i += 256) {
        atomicAdd(&hist[cmax[i] >> 20], 1u);
    }
    __syncthreads();

    unsigned s = 0;
#pragma unroll
    for (int j = 0; j < 16; j++) s += hist[tid * 16 + j];
    chs[tid] = s;
    __syncthreads();

    if (tid == 0) {
        // maximal T with #chunks(binkey >= T) >= TOPK. Guarantees every
        // top-50 element lives in a chunk whose max-bin >= T.
        unsigned cum = 0;
        int c = 255;
        for (; c >= 0; c--) {
            if (cum + chs[c] >= TOPK) break;
            cum += chs[c];
        }
        int T = c * 16;
        for (int d = c * 16 + 15; d >= c * 16; d--) {
            if (cum + hist[d] >= TOPK) { T = d; break; }
            cum += hist[d];
        }
        sT = T;
    }
    __syncthreads();
    const int T = sT;

    // phase 2: selected chunk list
    for (int i = tid; i < nchunks; i += 256) {
        if ((int)(cmax[i] >> 20) >= T) {
            unsigned p = atomicAdd(&sNch, 1u);
            if (p < 1024u) chlist[p] = i;
        }
    }
    __syncthreads();
    const int nch = (int)min(sNch, 1024u);

    // phase 3: candidates = elements of selected chunks with binkey >= T
    const float* row = g_scores + (size_t)b * M;
    for (int j = tid; j < nch * 32; j += 256) {
        const int chunk = chlist[j >> 5];
        const int col   = chunk * 32 + (j & 31);
        if (col < M) {
            float v = row[col];
            unsigned u = mono_u32(v);
            if ((int)(u >> 20) >= T) {
                unsigned p = atomicAdd(&sNc, 1u);
                if (p < 2048u) { cand_u[p] = u; cand_i[p] = col; cand_v[p] = v; }
            }
        }
    }
    __syncthreads();
    const int n = (int)min(sNc, 2048u);
    const int is64 = g_val_is64;
    const long long* v64 = (const long long*)values_raw;
    const int*       v32 = (const int*)values_raw;

    // exact top-50 (tie-break: score desc, index asc — matches lax.top_k)
    for (int it = 0; it < TOPK; it++) {
        unsigned long long best = 0ull;
        int bslot = -1;
        for (int j = tid; j < n; j += 256) {
            unsigned long long key =
                ((unsigned long long)cand_u[j] << 32) |
                (unsigned long long)(0xFFFFFFFFu - (unsigned)cand_i[j]);
            if (key > best) { best = key; bslot = j; }
        }
#pragma unroll
        for (int o = 16; o; o >>= 1) {
            unsigned long long ok = __shfl_xor_sync(0xffffffffu, best, o);
            int os = __shfl_xor_sync(0xffffffffu, bslot, o);
            if (ok > best) { best = ok; bslot = os; }
        }
        if (lane == 0) { redK[w] = best; redS[w] = bslot; }
        __syncthreads();
        if (tid == 0) {
            unsigned long long bb = 0ull;
            int ss2 = -1;
            for (int q = 0; q < 8; q++)
                if (redK[q] > bb) { bb = redK[q]; ss2 = redS[q]; }
            if (ss2 >= 0) {
                int idx = cand_i[ss2];
                int lbl = is64 ? (int)v64[idx] : v32[idx];
                if (lbl >= 0 && lbl < NCLS) cls[lbl] += cand_v[ss2];
                cand_u[ss2] = 0u;
            }
        }
        __syncthreads();
    }

    if (tid < NCLS) out[b * NCLS + tid] = cls[tid];
}

// ---------------- launcher ----------------
extern "C" void kernel_launch(void* const* d_in, const int* in_sizes, int n_in,
                              void* d_out, int out_size) {
    const float* x      = (const float*)d_in[0];
    const float* keys   = (const float*)d_in[1];
    const void*  values = d_in[2];
    float*       out    = (float*)d_out;

    const int B = in_sizes[0] / DD;   // 1024
    const int M = in_sizes[2];        // 60000
    const int nchunks = (M + 31) / 32;

    norm_split_kernel<<<B, 128>>>(x, 0);
    norm_split_kernel<<<M, 128>>>(keys, 1);
    detect_values_kernel<<<1, 1>>>(values);

    const int dyn_smem = NSTG * 128 * PADH * 2;   // 55296 B
    cudaFuncSetAttribute(gemm_kernel,
                         cudaFuncAttributeMaxDynamicSharedMemorySize, dyn_smem);
    dim3 grid(B / 128, (M + 127) / 128);
    gemm_kernel<<<grid, 128, dyn_smem>>>(M);

    topk_vote_kernel<<<B, 256>>>(values, out, M, nchunks);
}

// round 4
// speedup vs baseline: 1.5635x; 1.5635x over previous
#include <cuda_runtime.h>
#include <cuda_bf16.h>
#include <stdint.h>

// Problem shape (fixed by setup_inputs)
#define DD   512
#define BQ   1024
#define MKEY 60000
#define TOPK 50
#define NCLS 10
#define CHKSTR 1880      // per-row chunk-max stride (>= ceil(M/32))

// ---------------- device scratch (static, allocation-free) ----------------
__device__ alignas(128) __nv_bfloat16 g_xhi[(size_t)BQ * DD];
__device__ alignas(128) __nv_bfloat16 g_xlo[(size_t)BQ * DD];
__device__ alignas(128) __nv_bfloat16 g_khi[(size_t)MKEY * DD];
__device__ alignas(128) __nv_bfloat16 g_klo[(size_t)MKEY * DD];
__device__ float         g_scores[(size_t)BQ * MKEY];     // 245.8 MB
__device__ unsigned      g_cmax[(size_t)BQ * CHKSTR];     // 7.7 MB mono chunk maxima
__device__ int           g_val_is64;

// ---------------- PTX helpers ----------------
__device__ __forceinline__ uint32_t s2u(const void* p) {
    return (uint32_t)__cvta_generic_to_shared(p);
}
__device__ __forceinline__ void cpa16(uint32_t dst, const void* src, int sz) {
    asm volatile("cp.async.cg.shared.global [%0], [%1], 16, %2;\n"
                 :: "r"(dst), "l"(src), "r"(sz));
}
__device__ __forceinline__ void cp_commit() {
    asm volatile("cp.async.commit_group;\n");
}
template <int N>
__device__ __forceinline__ void cp_wait() {
    asm volatile("cp.async.wait_group %0;\n" :: "n"(N));
}
__device__ __forceinline__ void ldmx4(uint32_t* r, uint32_t a) {
    asm volatile("ldmatrix.sync.aligned.m8n8.x4.shared.b16 {%0,%1,%2,%3}, [%4];\n"
                 : "=r"(r[0]), "=r"(r[1]), "=r"(r[2]), "=r"(r[3]) : "r"(a));
}
__device__ __forceinline__ void mma_bf16(float* c, const uint32_t* a, const uint32_t* b) {
    asm volatile(
        "mma.sync.aligned.m16n8k16.row.col.f32.bf16.bf16.f32 "
        "{%0,%1,%2,%3},{%4,%5,%6,%7},{%8,%9},{%0,%1,%2,%3};\n"
        : "+f"(c[0]), "+f"(c[1]), "+f"(c[2]), "+f"(c[3])
        : "r"(a[0]), "r"(a[1]), "r"(a[2]), "r"(a[3]), "r"(b[0]), "r"(b[1]));
}
__device__ __forceinline__ unsigned mono_u32(float v) {
    unsigned u = __float_as_uint(v);
    return (u & 0x80000000u) ? ~u : (u | 0x80000000u);
}

// ---------------- normalize + bf16 split ----------------
__global__ void norm_split_kernel(const float* __restrict__ src, int which) {
    const int row = blockIdx.x;
    const int t   = threadIdx.x;               // 128 threads
    const float* r = src + (size_t)row * DD;

    float v[4];
    float ss = 0.f;
#pragma unroll
    for (int j = 0; j < 4; j++) {
        v[j] = r[t + 128 * j];
        ss += v[j] * v[j];
    }
#pragma unroll
    for (int o = 16; o; o >>= 1) ss += __shfl_xor_sync(0xffffffffu, ss, o);
    __shared__ float ws[4];
    if ((t & 31) == 0) ws[t >> 5] = ss;
    __syncthreads();
    const float tot = ws[0] + ws[1] + ws[2] + ws[3];
    const float inv = 1.0f / fmaxf(sqrtf(tot), 1e-12f);

    __nv_bfloat16* hi = which ? g_khi : g_xhi;
    __nv_bfloat16* lo = which ? g_klo : g_xlo;
#pragma unroll
    for (int j = 0; j < 4; j++) {
        float xn = v[j] * inv;
        __nv_bfloat16 h = __float2bfloat16(xn);
        float rem = xn - __bfloat162float(h);
        size_t o2 = (size_t)row * DD + t + 128 * j;
        hi[o2] = h;
        lo[o2] = __float2bfloat16(rem);
    }
}

// ---------------- values dtype sniffing (jax may demote int64 -> int32) ---
__global__ void detect_values_kernel(const void* vals) {
    const long long* p = (const long long*)vals;
    int ok = 1;
    for (int i = 0; i < 64; i++) {
        long long vv = p[i];
        if (vv < 0 || vv >= NCLS) { ok = 0; break; }
    }
    g_val_is64 = ok;
}

// ---------------- GEMM: scores = xhi*klo + xlo*khi + xhi*khi (K = 3*512) --
// CTA 128x128, 8 warps (2x4), warp tile 64x32, KT=32.
// 4-stage cp.async smem pipeline + register fragment double-buffering.
#define KT    32
#define PAD   40       // halves per smem row (32 data + 8 pad) -> 80B stride
#define NSTG  4
#define NTILE 48       // 1536 / 32
#define STAGE_H (128 * PAD)

__global__ void __launch_bounds__(256) gemm_kernel(int M) {
    extern __shared__ __align__(16) __nv_bfloat16 smem[];
    __nv_bfloat16* Asm = smem;                     // [NSTG][128*PAD]
    __nv_bfloat16* Bsm = smem + NSTG * STAGE_H;    // [NSTG][128*PAD]

    const int tid  = threadIdx.x;
    const int lane = tid & 31;
    const int w    = tid >> 5;
    const int wm   = w & 1;        // 0..1 -> 64-row slab
    const int wn   = w >> 1;       // 0..3 -> 32-col slab
    const int bm0  = blockIdx.x * 128;
    const int bn0  = blockIdx.y * 128;

    float acc[4][4][4];
#pragma unroll
    for (int a = 0; a < 4; a++)
#pragma unroll
        for (int b = 0; b < 4; b++)
#pragma unroll
            for (int c = 0; c < 4; c++) acc[a][b][c] = 0.f;

    uint32_t afr[2][4][4];
    uint32_t bfr[2][4][2];

    auto loadTile = [&](int t, int stg) {
        const int kk0  = t * KT;
        const int seg  = kk0 >> 9;        // 0: xhi*klo, 1: xlo*khi, 2: xhi*khi
        const int koff = kk0 & 511;
        const __nv_bfloat16* Asrc = (seg == 1) ? g_xlo : g_xhi;
        const __nv_bfloat16* Bsrc = (seg == 0) ? g_klo : g_khi;
        __nv_bfloat16* Ad = Asm + stg * STAGE_H;
        __nv_bfloat16* Bd = Bsm + stg * STAGE_H;
#pragma unroll
        for (int i = 0; i < 2; i++) {
            const int c   = tid + i * 256;   // 512 16B-chunks per tensor tile
            const int r   = c >> 2;
            const int sub = c & 3;
            cpa16(s2u(Ad + r * PAD + sub * 8),
                  Asrc + (size_t)(bm0 + r) * DD + koff + sub * 8, 16);
            const int gr = bn0 + r;
            const int ok = (gr < M) ? 16 : 0;
            cpa16(s2u(Bd + r * PAD + sub * 8),
                  Bsrc + (size_t)((gr < M) ? gr : 0) * DD + koff + sub * 8, ok);
        }
    };

    auto loadFrags = [&](int stg, int kh, int bb) {
        const __nv_bfloat16* Ab = Asm + stg * STAGE_H;
        const __nv_bfloat16* Bb = Bsm + stg * STAGE_H;
#pragma unroll
        for (int mt = 0; mt < 4; mt++) {
            const int r = wm * 64 + mt * 16 + (lane & 15);
            const int c = kh * 16 + ((lane >> 4) << 3);
            ldmx4(afr[bb][mt], s2u(Ab + r * PAD + c));
        }
        const int q = lane >> 3;
#pragma unroll
        for (int np = 0; np < 2; np++) {
            const int rr = wn * 32 + np * 16 + ((q >> 1) << 3) + (lane & 7);
            const int cc = kh * 16 + ((q & 1) << 3);
            uint32_t tmp[4];
            ldmx4(tmp, s2u(Bb + rr * PAD + cc));
            bfr[bb][np * 2 + 0][0] = tmp[0];
            bfr[bb][np * 2 + 0][1] = tmp[1];
            bfr[bb][np * 2 + 1][0] = tmp[2];
            bfr[bb][np * 2 + 1][1] = tmp[3];
        }
    };

    auto mmaAll = [&](int bb) {
#pragma unroll
        for (int mt = 0; mt < 4; mt++)
#pragma unroll
            for (int nt = 0; nt < 4; nt++)
                mma_bf16(acc[mt][nt], afr[bb][mt], bfr[bb][nt]);
    };

    // prologue: 3 stages in flight, first fragments resident
    loadTile(0, 0); cp_commit();
    loadTile(1, 1); cp_commit();
    loadTile(2, 2); cp_commit();
    cp_wait<2>();
    __syncthreads();
    loadFrags(0, 0, 0);

    for (int t = 0; t < NTILE; t++) {
        const int stg = t & (NSTG - 1);

        loadFrags(stg, 1, 1);          // kh=1 frags of this tile
        mmaAll(0);                     // kh=0 MMAs overlap the LDSMs above

        cp_wait<1>();                  // stage t+1 landed
        __syncthreads();               // all warps done reading stage t-1
        if (t + 1 < NTILE) loadFrags((t + 1) & (NSTG - 1), 0, 0);

        mmaAll(1);                     // kh=1 MMAs overlap next-tile LDSMs

        if (t + 3 < NTILE) loadTile(t + 3, (t + 3) & (NSTG - 1));
        cp_commit();
    }

    // ---------------- epilogue: scores (float2) + per-32-chunk row maxima --
#pragma unroll
    for (int mt = 0; mt < 4; mt++) {
        const int r0 = bm0 + wm * 64 + mt * 16 + (lane >> 2);
#pragma unroll
        for (int nt = 0; nt < 4; nt++) {
            const int c0 = bn0 + wn * 32 + nt * 8 + (lane & 3) * 2;
            if (c0 < M) {
                float2 v0 = make_float2(acc[mt][nt][0], acc[mt][nt][1]);
                float2 v1 = make_float2(acc[mt][nt][2], acc[mt][nt][3]);
                *(float2*)&g_scores[(size_t)r0 * M + c0]       = v0;
                *(float2*)&g_scores[(size_t)(r0 + 8) * M + c0] = v1;
            }
        }
        // 32-col chunk maxima (one chunk per warp slab)
        float m0 = -1e30f, m1 = -1e30f;
#pragma unroll
        for (int nt = 0; nt < 4; nt++) {
            m0 = fmaxf(m0, fmaxf(acc[mt][nt][0], acc[mt][nt][1]));
            m1 = fmaxf(m1, fmaxf(acc[mt][nt][2], acc[mt][nt][3]));
        }
        m0 = fmaxf(m0, __shfl_xor_sync(0xffffffffu, m0, 1));
        m0 = fmaxf(m0, __shfl_xor_sync(0xffffffffu, m0, 2));
        m1 = fmaxf(m1, __shfl_xor_sync(0xffffffffu, m1, 1));
        m1 = fmaxf(m1, __shfl_xor_sync(0xffffffffu, m1, 2));
        const int cbase = bn0 + wn * 32;
        if ((lane & 3) == 0 && cbase < M) {
            g_cmax[(size_t)r0 * CHKSTR + (cbase >> 5)]       = mono_u32(m0);
            g_cmax[(size_t)(r0 + 8) * CHKSTR + (cbase >> 5)] = mono_u32(m1);
        }
    }
}

// ---------------- per-row top-k + class vote (chunk-max pruned) -----------
__global__ void __launch_bounds__(256) topk_vote_kernel(
    const void* __restrict__ values_raw, float* __restrict__ out,
    int M, int nchunks) {
    const int b    = blockIdx.x;
    const int tid  = threadIdx.x;
    const int lane = tid & 31;
    const int w    = tid >> 5;

    __shared__ unsigned hist[4096];
    __shared__ unsigned chs[256];
    __shared__ int      sT;
    __shared__ unsigned sNc, sNch;
    __shared__ int      chlist[1024];
    __shared__ unsigned cand_u[2048];
    __shared__ int      cand_i[2048];
    __shared__ float    cand_v[2048];
    __shared__ unsigned long long redK[8];
    __shared__ int      redS[8];
    __shared__ float    cls[NCLS];

    for (int i = tid; i < 4096; i += 256) hist[i] = 0u;
    if (tid < NCLS) cls[tid] = 0.f;
    if (tid == 0) { sNc = 0u; sNch = 0u; }
    __syncthreads();

    const unsigned* cmax = g_cmax + (size_t)b * CHKSTR;

    // phase 1: histogram of chunk maxima (12-bit radix over mono bits)
    for (int i = tid; i < nchunks; i += 256) {
        atomicAdd(&hist[cmax[i] >> 20], 1u);
    }
    __syncthreads();

    unsigned s = 0;
#pragma unroll
    for (int j = 0; j < 16; j++) s += hist[tid * 16 + j];
    chs[tid] = s;
    __syncthreads();

    if (tid == 0) {
        unsigned cum = 0;
        int c = 255;
        for (; c >= 0; c--) {
            if (cum + chs[c] >= TOPK) break;
            cum += chs[c];
        }
        int T = c * 16;
        for (int d = c * 16 + 15; d >= c * 16; d--) {
            if (cum + hist[d] >= TOPK) { T = d; break; }
            cum += hist[d];
        }
        sT = T;
    }
    __syncthreads();
    const int T = sT;

    // phase 2: selected chunk list
    for (int i = tid; i < nchunks; i += 256) {
        if ((int)(cmax[i] >> 20) >= T) {
            unsigned p = atomicAdd(&sNch, 1u);
            if (p < 1024u) chlist[p] = i;
        }
    }
    __syncthreads();
    const int nch = (int)min(sNch, 1024u);

    // phase 3: candidates = elements of selected chunks with binkey >= T
    const float* row = g_scores + (size_t)b * M;
    for (int j = tid; j < nch * 32; j += 256) {
        const int chunk = chlist[j >> 5];
        const int col   = chunk * 32 + (j & 31);
        if (col < M) {
            float v = row[col];
            unsigned u = mono_u32(v);
            if ((int)(u >> 20) >= T) {
                unsigned p = atomicAdd(&sNc, 1u);
                if (p < 2048u) { cand_u[p] = u; cand_i[p] = col; cand_v[p] = v; }
            }
        }
    }
    __syncthreads();
    const int n = (int)min(sNc, 2048u);
    const int is64 = g_val_is64;
    const long long* v64 = (const long long*)values_raw;
    const int*       v32 = (const int*)values_raw;

    // exact top-50 (tie-break: score desc, index asc — matches lax.top_k)
    for (int it = 0; it < TOPK; it++) {
        unsigned long long best = 0ull;
        int bslot = -1;
        for (int j = tid; j < n; j += 256) {
            unsigned long long key =
                ((unsigned long long)cand_u[j] << 32) |
                (unsigned long long)(0xFFFFFFFFu - (unsigned)cand_i[j]);
            if (key > best) { best = key; bslot = j; }
        }
#pragma unroll
        for (int o = 16; o; o >>= 1) {
            unsigned long long ok = __shfl_xor_sync(0xffffffffu, best, o);
            int os = __shfl_xor_sync(0xffffffffu, bslot, o);
            if (ok > best) { best = ok; bslot = os; }
        }
        if (lane == 0) { redK[w] = best; redS[w] = bslot; }
        __syncthreads();
        if (tid == 0) {
            unsigned long long bb = 0ull;
            int ss2 = -1;
            for (int q = 0; q < 8; q++)
                if (redK[q] > bb) { bb = redK[q]; ss2 = redS[q]; }
            if (ss2 >= 0) {
                int idx = cand_i[ss2];
                int lbl = is64 ? (int)v64[idx] : v32[idx];
                if (lbl >= 0 && lbl < NCLS) cls[lbl] += cand_v[ss2];
                cand_u[ss2] = 0u;
            }
        }
        __syncthreads();
    }

    if (tid < NCLS) out[b * NCLS + tid] = cls[tid];
}

// ---------------- launcher ----------------
extern "C" void kernel_launch(void* const* d_in, const int* in_sizes, int n_in,
                              void* d_out, int out_size) {
    const float* x      = (const float*)d_in[0];
    const float* keys   = (const float*)d_in[1];
    const void*  values = d_in[2];
    float*       out    = (float*)d_out;

    const int B = in_sizes[0] / DD;   // 1024
    const int M = in_sizes[2];        // 60000
    const int nchunks = (M + 31) / 32;

    norm_split_kernel<<<B, 128>>>(x, 0);
    norm_split_kernel<<<M, 128>>>(keys, 1);
    detect_values_kernel<<<1, 1>>>(values);

    const int dyn_smem = NSTG * STAGE_H * 2 * (int)sizeof(__nv_bfloat16); // 81920 B
    cudaFuncSetAttribute(gemm_kernel,
                         cudaFuncAttributeMaxDynamicSharedMemorySize, dyn_smem);
    dim3 grid(B / 128, (M + 127) / 128);
    gemm_kernel<<<grid, 256, dyn_smem>>>(M);

    topk_vote_kernel<<<B, 256>>>(values, out, M, nchunks);
}

// round 5
// speedup vs baseline: 1.7213x; 1.1009x over previous
#include <cuda_runtime.h>
#include <cuda_bf16.h>
#include <stdint.h>

// Problem shape (fixed by setup_inputs)
#define DD   512
#define BQ   1024
#define MKEY 60000
#define TOPK 50
#define NCLS 10
#define CHKSTR 1880      // per-row chunk-max stride (>= ceil(M/32))

// ---------------- device scratch (static, allocation-free) ----------------
__device__ alignas(128) __nv_bfloat16 g_xhi[(size_t)BQ * DD];
__device__ alignas(128) __nv_bfloat16 g_xlo[(size_t)BQ * DD];
__device__ alignas(128) __nv_bfloat16 g_khi[(size_t)MKEY * DD];
__device__ alignas(128) __nv_bfloat16 g_klo[(size_t)MKEY * DD];
__device__ float         g_scores[(size_t)BQ * MKEY];     // 245.8 MB
__device__ unsigned      g_cmax[(size_t)BQ * CHKSTR];     // 7.7 MB mono chunk maxima
__device__ int           g_val_is64;

// ---------------- PTX helpers ----------------
__device__ __forceinline__ uint32_t s2u(const void* p) {
    return (uint32_t)__cvta_generic_to_shared(p);
}
__device__ __forceinline__ void cpa16(uint32_t dst, const void* src, int sz) {
    asm volatile("cp.async.cg.shared.global [%0], [%1], 16, %2;\n"
                 :: "r"(dst), "l"(src), "r"(sz));
}
__device__ __forceinline__ void cp_commit() {
    asm volatile("cp.async.commit_group;\n");
}
template <int N>
__device__ __forceinline__ void cp_wait() {
    asm volatile("cp.async.wait_group %0;\n" :: "n"(N));
}
__device__ __forceinline__ void ldmx4(uint32_t* r, uint32_t a) {
    asm volatile("ldmatrix.sync.aligned.m8n8.x4.shared.b16 {%0,%1,%2,%3}, [%4];\n"
                 : "=r"(r[0]), "=r"(r[1]), "=r"(r[2]), "=r"(r[3]) : "r"(a));
}
__device__ __forceinline__ void mma_bf16(float* c, const uint32_t* a, const uint32_t* b) {
    asm volatile(
        "mma.sync.aligned.m16n8k16.row.col.f32.bf16.bf16.f32 "
        "{%0,%1,%2,%3},{%4,%5,%6,%7},{%8,%9},{%0,%1,%2,%3};\n"
        : "+f"(c[0]), "+f"(c[1]), "+f"(c[2]), "+f"(c[3])
        : "r"(a[0]), "r"(a[1]), "r"(a[2]), "r"(a[3]), "r"(b[0]), "r"(b[1]));
}
__device__ __forceinline__ unsigned mono_u32(float v) {
    unsigned u = __float_as_uint(v);
    return (u & 0x80000000u) ? ~u : (u | 0x80000000u);
}

// ---------------- normalize + bf16 split ----------------
__global__ void norm_split_kernel(const float* __restrict__ src, int which) {
    const int row = blockIdx.x;
    const int t   = threadIdx.x;               // 128 threads
    const float* r = src + (size_t)row * DD;

    float v[4];
    float ss = 0.f;
#pragma unroll
    for (int j = 0; j < 4; j++) {
        v[j] = r[t + 128 * j];
        ss += v[j] * v[j];
    }
#pragma unroll
    for (int o = 16; o; o >>= 1) ss += __shfl_xor_sync(0xffffffffu, ss, o);
    __shared__ float ws[4];
    if ((t & 31) == 0) ws[t >> 5] = ss;
    __syncthreads();
    const float tot = ws[0] + ws[1] + ws[2] + ws[3];
    const float inv = 1.0f / fmaxf(sqrtf(tot), 1e-12f);

    __nv_bfloat16* hi = which ? g_khi : g_xhi;
    __nv_bfloat16* lo = which ? g_klo : g_xlo;
#pragma unroll
    for (int j = 0; j < 4; j++) {
        float xn = v[j] * inv;
        __nv_bfloat16 h = __float2bfloat16(xn);
        float rem = xn - __bfloat162float(h);
        size_t o2 = (size_t)row * DD + t + 128 * j;
        hi[o2] = h;
        lo[o2] = __float2bfloat16(rem);
    }
}

// ---------------- values dtype sniffing (jax may demote int64 -> int32) ---
__global__ void detect_values_kernel(const void* vals) {
    const long long* p = (const long long*)vals;
    int ok = 1;
    for (int i = 0; i < 64; i++) {
        long long vv = p[i];
        if (vv < 0 || vv >= NCLS) { ok = 0; break; }
    }
    g_val_is64 = ok;
}

// ---------------- GEMM: scores = xhi*klo + xlo*khi + xhi*khi (K = 3*512) --
// CTA tile 256x128, 8 warps (4x2), warp tile 64x64, KT=32.
// 4-stage cp.async smem pipeline + register fragment double-buffering.
#define KT    32
#define PAD   40                  // halves per smem row (32 data + 8 pad)
#define NSTG  4
#define NTILE 48                  // 1536 / 32
#define A_H   (256 * PAD)         // halves per A stage
#define B_H   (128 * PAD)         // halves per B stage
#define STAGE_H (A_H + B_H)

__global__ void __launch_bounds__(256, 1) gemm_kernel(int M) {
    extern __shared__ __align__(16) __nv_bfloat16 smem[];   // [NSTG][A_H+B_H]

    const int tid  = threadIdx.x;
    const int lane = tid & 31;
    const int w    = tid >> 5;
    const int wm   = w >> 1;       // 0..3 -> 64-row slab
    const int wn   = w & 1;        // 0..1 -> 64-col slab
    const int bm0  = blockIdx.x * 256;
    const int bn0  = blockIdx.y * 128;

    float acc[4][8][4];
#pragma unroll
    for (int a = 0; a < 4; a++)
#pragma unroll
        for (int b = 0; b < 8; b++)
#pragma unroll
            for (int c = 0; c < 4; c++) acc[a][b][c] = 0.f;

    uint32_t afr[2][4][4];
    uint32_t bfr[2][8][2];

    auto loadTile = [&](int t, int stg) {
        const int kk0  = t * KT;
        const int seg  = kk0 >> 9;        // 0: xhi*klo, 1: xlo*khi, 2: xhi*khi
        const int koff = kk0 & 511;
        const __nv_bfloat16* Asrc = (seg == 1) ? g_xlo : g_xhi;
        const __nv_bfloat16* Bsrc = (seg == 0) ? g_klo : g_khi;
        __nv_bfloat16* Ad = smem + stg * STAGE_H;
        __nv_bfloat16* Bd = Ad + A_H;
        // A: 256 rows * 4 chunks = 1024 chunks of 16B
#pragma unroll
        for (int i = 0; i < 4; i++) {
            const int c   = tid + i * 256;
            const int r   = c >> 2;
            const int sub = c & 3;
            cpa16(s2u(Ad + r * PAD + sub * 8),
                  Asrc + (size_t)(bm0 + r) * DD + koff + sub * 8, 16);
        }
        // B: 128 rows * 4 chunks = 512 chunks of 16B
#pragma unroll
        for (int i = 0; i < 2; i++) {
            const int c   = tid + i * 256;
            const int r   = c >> 2;
            const int sub = c & 3;
            const int gr  = bn0 + r;
            const int ok  = (gr < M) ? 16 : 0;
            cpa16(s2u(Bd + r * PAD + sub * 8),
                  Bsrc + (size_t)((gr < M) ? gr : 0) * DD + koff + sub * 8, ok);
        }
    };

    auto loadFrags = [&](int stg, int kh, int bb) {
        const __nv_bfloat16* Ab = smem + stg * STAGE_H;
        const __nv_bfloat16* Bb = Ab + A_H;
#pragma unroll
        for (int mt = 0; mt < 4; mt++) {
            const int r = wm * 64 + mt * 16 + (lane & 15);
            const int c = kh * 16 + ((lane >> 4) << 3);
            ldmx4(afr[bb][mt], s2u(Ab + r * PAD + c));
        }
        const int q = lane >> 3;
#pragma unroll
        for (int np = 0; np < 4; np++) {
            const int rr = wn * 64 + np * 16 + ((q >> 1) << 3) + (lane & 7);
            const int cc = kh * 16 + ((q & 1) << 3);
            uint32_t tmp[4];
            ldmx4(tmp, s2u(Bb + rr * PAD + cc));
            bfr[bb][np * 2 + 0][0] = tmp[0];
            bfr[bb][np * 2 + 0][1] = tmp[1];
            bfr[bb][np * 2 + 1][0] = tmp[2];
            bfr[bb][np * 2 + 1][1] = tmp[3];
        }
    };

    auto mmaAll = [&](int bb) {
#pragma unroll
        for (int mt = 0; mt < 4; mt++)
#pragma unroll
            for (int nt = 0; nt < 8; nt++)
                mma_bf16(acc[mt][nt], afr[bb][mt], bfr[bb][nt]);
    };

    // prologue: 3 stages in flight, first fragments resident
    loadTile(0, 0); cp_commit();
    loadTile(1, 1); cp_commit();
    loadTile(2, 2); cp_commit();
    cp_wait<2>();
    __syncthreads();
    loadFrags(0, 0, 0);

    for (int t = 0; t < NTILE; t++) {
        const int stg = t & (NSTG - 1);

        loadFrags(stg, 1, 1);          // kh=1 frags of this tile
        mmaAll(0);                     // kh=0 MMAs overlap the LDSMs above

        cp_wait<1>();                  // stage t+1 landed
        __syncthreads();               // all warps done reading stage t-1
        if (t + 1 < NTILE) loadFrags((t + 1) & (NSTG - 1), 0, 0);

        mmaAll(1);                     // kh=1 MMAs overlap next-tile LDSMs

        if (t + 3 < NTILE) loadTile(t + 3, (t + 3) & (NSTG - 1));
        cp_commit();
    }

    // ---------------- epilogue: scores (float2) + per-32-chunk row maxima --
#pragma unroll
    for (int mt = 0; mt < 4; mt++) {
        const int r0 = bm0 + wm * 64 + mt * 16 + (lane >> 2);
#pragma unroll
        for (int nt = 0; nt < 8; nt++) {
            const int c0 = bn0 + wn * 64 + nt * 8 + (lane & 3) * 2;
            if (c0 < M) {
                float2 v0 = make_float2(acc[mt][nt][0], acc[mt][nt][1]);
                float2 v1 = make_float2(acc[mt][nt][2], acc[mt][nt][3]);
                *(float2*)&g_scores[(size_t)r0 * M + c0]       = v0;
                *(float2*)&g_scores[(size_t)(r0 + 8) * M + c0] = v1;
            }
        }
        // two 32-col chunk maxima per warp slab
#pragma unroll
        for (int cg = 0; cg < 2; cg++) {
            float m0 = -1e30f, m1 = -1e30f;
#pragma unroll
            for (int j = 0; j < 4; j++) {
                const int nt = cg * 4 + j;
                m0 = fmaxf(m0, fmaxf(acc[mt][nt][0], acc[mt][nt][1]));
                m1 = fmaxf(m1, fmaxf(acc[mt][nt][2], acc[mt][nt][3]));
            }
            m0 = fmaxf(m0, __shfl_xor_sync(0xffffffffu, m0, 1));
            m0 = fmaxf(m0, __shfl_xor_sync(0xffffffffu, m0, 2));
            m1 = fmaxf(m1, __shfl_xor_sync(0xffffffffu, m1, 1));
            m1 = fmaxf(m1, __shfl_xor_sync(0xffffffffu, m1, 2));
            const int cbase = bn0 + wn * 64 + cg * 32;
            if ((lane & 3) == 0 && cbase < M) {
                g_cmax[(size_t)r0 * CHKSTR + (cbase >> 5)]       = mono_u32(m0);
                g_cmax[(size_t)(r0 + 8) * CHKSTR + (cbase >> 5)] = mono_u32(m1);
            }
        }
    }
}

// ---------------- per-row top-k + class vote (chunk-max pruned) -----------
__global__ void __launch_bounds__(256) topk_vote_kernel(
    const void* __restrict__ values_raw, float* __restrict__ out,
    int M, int nchunks) {
    const int b    = blockIdx.x;
    const int tid  = threadIdx.x;
    const int lane = tid & 31;
    const int w    = tid >> 5;

    __shared__ unsigned hist[4096];
    __shared__ unsigned chs[256];
    __shared__ int      sT;
    __shared__ unsigned sNc, sNch;
    __shared__ int      chlist[1024];
    __shared__ unsigned cand_u[2048];
    __shared__ int      cand_i[2048];
    __shared__ float    cand_v[2048];
    __shared__ unsigned long long redK[8];
    __shared__ int      redS[8];
    __shared__ float    cls[NCLS];

    for (int i = tid; i < 4096; i += 256) hist[i] = 0u;
    if (tid < NCLS) cls[tid] = 0.f;
    if (tid == 0) { sNc = 0u; sNch = 0u; }
    __syncthreads();

    const unsigned* cmax = g_cmax + (size_t)b * CHKSTR;

    // phase 1: histogram of chunk maxima (12-bit radix over mono bits)
    for (int i = tid; i < nchunks; i += 256) {
        atomicAdd(&hist[cmax[i] >> 20], 1u);
    }
    __syncthreads();

    unsigned s = 0;
#pragma unroll
    for (int j = 0; j < 16; j++) s += hist[tid * 16 + j];
    chs[tid] = s;
    __syncthreads();

    if (tid == 0) {
        unsigned cum = 0;
        int c = 255;
        for (; c >= 0; c--) {
            if (cum + chs[c] >= TOPK) break;
            cum += chs[c];
        }
        int T = c * 16;
        for (int d = c * 16 + 15; d >= c * 16; d--) {
            if (cum + hist[d] >= TOPK) { T = d; break; }
            cum += hist[d];
        }
        sT = T;
    }
    __syncthreads();
    const int T = sT;

    // phase 2: selected chunk list
    for (int i = tid; i < nchunks; i += 256) {
        if ((int)(cmax[i] >> 20) >= T) {
            unsigned p = atomicAdd(&sNch, 1u);
            if (p < 1024u) chlist[p] = i;
        }
    }
    __syncthreads();
    const int nch = (int)min(sNch, 1024u);

    // phase 3: candidates = elements of selected chunks with binkey >= T
    const float* row = g_scores + (size_t)b * M;
    for (int j = tid; j < nch * 32; j += 256) {
        const int chunk = chlist[j >> 5];
        const int col   = chunk * 32 + (j & 31);
        if (col < M) {
            float v = row[col];
            unsigned u = mono_u32(v);
            if ((int)(u >> 20) >= T) {
                unsigned p = atomicAdd(&sNc, 1u);
                if (p < 2048u) { cand_u[p] = u; cand_i[p] = col; cand_v[p] = v; }
            }
        }
    }
    __syncthreads();
    const int n = (int)min(sNc, 2048u);
    const int is64 = g_val_is64;
    const long long* v64 = (const long long*)values_raw;
    const int*       v32 = (const int*)values_raw;

    // exact top-50 (tie-break: score desc, index asc — matches lax.top_k)
    for (int it = 0; it < TOPK; it++) {
        unsigned long long best = 0ull;
        int bslot = -1;
        for (int j = tid; j < n; j += 256) {
            unsigned long long key =
                ((unsigned long long)cand_u[j] << 32) |
                (unsigned long long)(0xFFFFFFFFu - (unsigned)cand_i[j]);
            if (key > best) { best = key; bslot = j; }
        }
#pragma unroll
        for (int o = 16; o; o >>= 1) {
            unsigned long long ok = __shfl_xor_sync(0xffffffffu, best, o);
            int os = __shfl_xor_sync(0xffffffffu, bslot, o);
            if (ok > best) { best = ok; bslot = os; }
        }
        if (lane == 0) { redK[w] = best; redS[w] = bslot; }
        __syncthreads();
        if (tid == 0) {
            unsigned long long bb = 0ull;
            int ss2 = -1;
            for (int q = 0; q < 8; q++)
                if (redK[q] > bb) { bb = redK[q]; ss2 = redS[q]; }
            if (ss2 >= 0) {
                int idx = cand_i[ss2];
                int lbl = is64 ? (int)v64[idx] : v32[idx];
                if (lbl >= 0 && lbl < NCLS) cls[lbl] += cand_v[ss2];
                cand_u[ss2] = 0u;
            }
        }
        __syncthreads();
    }

    if (tid < NCLS) out[b * NCLS + tid] = cls[tid];
}

// ---------------- launcher ----------------
extern "C" void kernel_launch(void* const* d_in, const int* in_sizes, int n_in,
                              void* d_out, int out_size) {
    const float* x      = (const float*)d_in[0];
    const float* keys   = (const float*)d_in[1];
    const void*  values = d_in[2];
    float*       out    = (float*)d_out;

    const int B = in_sizes[0] / DD;   // 1024
    const int M = in_sizes[2];        // 60000
    const int nchunks = (M + 31) / 32;

    norm_split_kernel<<<B, 128>>>(x, 0);
    norm_split_kernel<<<M, 128>>>(keys, 1);
    detect_values_kernel<<<1, 1>>>(values);

    const int dyn_smem = NSTG * STAGE_H * (int)sizeof(__nv_bfloat16); // 122880 B
    cudaFuncSetAttribute(gemm_kernel,
                         cudaFuncAttributeMaxDynamicSharedMemorySize, dyn_smem);
    dim3 grid(B / 256, (M + 127) / 128);
    gemm_kernel<<<grid, 256, dyn_smem>>>(M);

    topk_vote_kernel<<<B, 256>>>(values, out, M, nchunks);
}

// round 7
// speedup vs baseline: 2.4473x; 1.4218x over previous
#include <cuda_runtime.h>
#include <cuda_bf16.h>
#include <stdint.h>

// Problem shape (fixed by setup_inputs)
#define DD   512
#define BQ   1024
#define MKEY 60000
#define TOPK 50
#define NCLS 10
#define CHKSTR 1880      // per-row chunk-max stride (>= ceil(M/32))
#define MARGIN 0.003f    // coverage margin over coarse bf16 score error (~43 sigma)

// ---------------- device scratch (static, allocation-free) ----------------
__device__ alignas(128) float          g_xn  [(size_t)BQ * DD];    // normalized x (fp32)
__device__ alignas(128) __nv_bfloat16  g_xhi [(size_t)BQ * DD];
__device__ alignas(128) __nv_bfloat16  g_khi [(size_t)MKEY * DD];
__device__ alignas(128) float          g_kinv[(size_t)MKEY];
__device__ unsigned short g_scores16[(size_t)BQ * MKEY];           // 122.9 MB mono>>16
__device__ unsigned short g_cmax16  [(size_t)BQ * CHKSTR];         // 3.85 MB
__device__ int            g_val_is64;

// ---------------- PTX helpers ----------------
__device__ __forceinline__ uint32_t s2u(const void* p) {
    return (uint32_t)__cvta_generic_to_shared(p);
}
__device__ __forceinline__ void cpa16(uint32_t dst, const void* src, int sz) {
    asm volatile("cp.async.cg.shared.global [%0], [%1], 16, %2;\n"
                 :: "r"(dst), "l"(src), "r"(sz));
}
__device__ __forceinline__ void cp_commit() {
    asm volatile("cp.async.commit_group;\n");
}
template <int N>
__device__ __forceinline__ void cp_wait() {
    asm volatile("cp.async.wait_group %0;\n" :: "n"(N));
}
__device__ __forceinline__ void ldmx4(uint32_t* r, uint32_t a) {
    asm volatile("ldmatrix.sync.aligned.m8n8.x4.shared.b16 {%0,%1,%2,%3}, [%4];\n"
                 : "=r"(r[0]), "=r"(r[1]), "=r"(r[2]), "=r"(r[3]) : "r"(a));
}
__device__ __forceinline__ void mma_bf16(float* c, const uint32_t* a, const uint32_t* b) {
    asm volatile(
        "mma.sync.aligned.m16n8k16.row.col.f32.bf16.bf16.f32 "
        "{%0,%1,%2,%3},{%4,%5,%6,%7},{%8,%9},{%0,%1,%2,%3};\n"
        : "+f"(c[0]), "+f"(c[1]), "+f"(c[2]), "+f"(c[3])
        : "r"(a[0]), "r"(a[1]), "r"(a[2]), "r"(a[3]), "r"(b[0]), "r"(b[1]));
}
__device__ __forceinline__ unsigned mono_u32(float v) {
    unsigned u = __float_as_uint(v);
    return (u & 0x80000000u) ? ~u : (u | 0x80000000u);
}
__device__ __forceinline__ float inv_mono(unsigned m) {
    unsigned u = (m & 0x80000000u) ? (m ^ 0x80000000u) : ~m;
    return __uint_as_float(u);
}

// ---------------- normalize kernels ----------------
__global__ void norm_x_kernel(const float* __restrict__ src) {
    const int row = blockIdx.x;
    const int t   = threadIdx.x;               // 128 threads
    const float* r = src + (size_t)row * DD;

    float v[4];
    float ss = 0.f;
#pragma unroll
    for (int j = 0; j < 4; j++) { v[j] = r[t + 128 * j]; ss += v[j] * v[j]; }
#pragma unroll
    for (int o = 16; o; o >>= 1) ss += __shfl_xor_sync(0xffffffffu, ss, o);
    __shared__ float ws[4];
    if ((t & 31) == 0) ws[t >> 5] = ss;
    __syncthreads();
    const float inv = 1.0f / fmaxf(sqrtf(ws[0] + ws[1] + ws[2] + ws[3]), 1e-12f);
#pragma unroll
    for (int j = 0; j < 4; j++) {
        float xn = v[j] * inv;
        size_t o2 = (size_t)row * DD + t + 128 * j;
        g_xn[o2]  = xn;
        g_xhi[o2] = __float2bfloat16(xn);
    }
}

__global__ void norm_k_kernel(const float* __restrict__ src) {
    const int row = blockIdx.x;
    const int t   = threadIdx.x;               // 128 threads
    const float* r = src + (size_t)row * DD;

    float v[4];
    float ss = 0.f;
#pragma unroll
    for (int j = 0; j < 4; j++) { v[j] = r[t + 128 * j]; ss += v[j] * v[j]; }
#pragma unroll
    for (int o = 16; o; o >>= 1) ss += __shfl_xor_sync(0xffffffffu, ss, o);
    __shared__ float ws[4];
    if ((t & 31) == 0) ws[t >> 5] = ss;
    __syncthreads();
    const float inv = 1.0f / fmaxf(sqrtf(ws[0] + ws[1] + ws[2] + ws[3]), 1e-12f);
    if (t == 0) g_kinv[row] = inv;
#pragma unroll
    for (int j = 0; j < 4; j++) {
        g_khi[(size_t)row * DD + t + 128 * j] = __float2bfloat16(v[j] * inv);
    }
}

// ---------------- values dtype sniffing (jax may demote int64 -> int32) ---
__global__ void detect_values_kernel(const void* vals) {
    const long long* p = (const long long*)vals;
    int ok = 1;
    for (int i = 0; i < 64; i++) {
        long long vv = p[i];
        if (vv < 0 || vv >= NCLS) { ok = 0; break; }
    }
    g_val_is64 = ok;
}

// ---------------- coarse GEMM: scores16 = mono(xhi . khi) >> 16 (K=512) ---
// CTA tile 256x128, 8 warps (4x2), warp tile 64x64, KT=32.
// 4-stage cp.async smem pipeline + register fragment double-buffering.
#define KT    32
#define PAD   40                  // halves per smem row (32 data + 8 pad)
#define NSTG  4
#define NTILE 16                  // 512 / 32
#define A_H   (256 * PAD)
#define B_H   (128 * PAD)
#define STAGE_H (A_H + B_H)

__global__ void __launch_bounds__(256, 1) gemm_kernel(int M) {
    extern __shared__ __align__(16) __nv_bfloat16 smem[];   // [NSTG][A_H+B_H]

    const int tid  = threadIdx.x;
    const int lane = tid & 31;
    const int w    = tid >> 5;
    const int wm   = w >> 1;       // 0..3 -> 64-row slab
    const int wn   = w & 1;        // 0..1 -> 64-col slab
    const int bm0  = blockIdx.x * 256;
    const int bn0  = blockIdx.y * 128;

    float acc[4][8][4];
#pragma unroll
    for (int a = 0; a < 4; a++)
#pragma unroll
        for (int b = 0; b < 8; b++)
#pragma unroll
            for (int c = 0; c < 4; c++) acc[a][b][c] = 0.f;

    uint32_t afr[2][4][4];
    uint32_t bfr[2][8][2];

    auto loadTile = [&](int t, int stg) {
        const int koff = t * KT;
        __nv_bfloat16* Ad = smem + stg * STAGE_H;
        __nv_bfloat16* Bd = Ad + A_H;
#pragma unroll
        for (int i = 0; i < 4; i++) {                // A: 1024 16B chunks
            const int c   = tid + i * 256;
            const int r   = c >> 2;
            const int sub = c & 3;
            cpa16(s2u(Ad + r * PAD + sub * 8),
                  g_xhi + (size_t)(bm0 + r) * DD + koff + sub * 8, 16);
        }
#pragma unroll
        for (int i = 0; i < 2; i++) {                // B: 512 16B chunks
            const int c   = tid + i * 256;
            const int r   = c >> 2;
            const int sub = c & 3;
            const int gr  = bn0 + r;
            const int ok  = (gr < M) ? 16 : 0;
            cpa16(s2u(Bd + r * PAD + sub * 8),
                  g_khi + (size_t)((gr < M) ? gr : 0) * DD + koff + sub * 8, ok);
        }
    };

    auto loadFrags = [&](int stg, int kh, int bb) {
        const __nv_bfloat16* Ab = smem + stg * STAGE_H;
        const __nv_bfloat16* Bb = Ab + A_H;
#pragma unroll
        for (int mt = 0; mt < 4; mt++) {
            const int r = wm * 64 + mt * 16 + (lane & 15);
            const int c = kh * 16 + ((lane >> 4) << 3);
            ldmx4(afr[bb][mt], s2u(Ab + r * PAD + c));
        }
        const int q = lane >> 3;
#pragma unroll
        for (int np = 0; np < 4; np++) {
            const int rr = wn * 64 + np * 16 + ((q >> 1) << 3) + (lane & 7);
            const int cc = kh * 16 + ((q & 1) << 3);
            uint32_t tmp[4];
            ldmx4(tmp, s2u(Bb + rr * PAD + cc));
            bfr[bb][np * 2 + 0][0] = tmp[0];
            bfr[bb][np * 2 + 0][1] = tmp[1];
            bfr[bb][np * 2 + 1][0] = tmp[2];
            bfr[bb][np * 2 + 1][1] = tmp[3];
        }
    };

    auto mmaAll = [&](int bb) {
#pragma unroll
        for (int mt = 0; mt < 4; mt++)
#pragma unroll
            for (int nt = 0; nt < 8; nt++)
                mma_bf16(acc[mt][nt], afr[bb][mt], bfr[bb][nt]);
    };

    loadTile(0, 0); cp_commit();
    loadTile(1, 1); cp_commit();
    loadTile(2, 2); cp_commit();
    cp_wait<2>();
    __syncthreads();
    loadFrags(0, 0, 0);

    for (int t = 0; t < NTILE; t++) {
        const int stg = t & (NSTG - 1);

        loadFrags(stg, 1, 1);
        mmaAll(0);

        cp_wait<1>();
        __syncthreads();
        if (t + 1 < NTILE) loadFrags((t + 1) & (NSTG - 1), 0, 0);

        mmaAll(1);

        if (t + 3 < NTILE) loadTile(t + 3, (t + 3) & (NSTG - 1));
        cp_commit();
    }

    // epilogue: u16 mono scores + u16 chunk maxima
#pragma unroll
    for (int mt = 0; mt < 4; mt++) {
        const int r0 = bm0 + wm * 64 + mt * 16 + (lane >> 2);
#pragma unroll
        for (int nt = 0; nt < 8; nt++) {
            const int c0 = bn0 + wn * 64 + nt * 8 + (lane & 3) * 2;
            if (c0 < M) {
                ushort2 u0, u1;
                u0.x = (unsigned short)(mono_u32(acc[mt][nt][0]) >> 16);
                u0.y = (unsigned short)(mono_u32(acc[mt][nt][1]) >> 16);
                u1.x = (unsigned short)(mono_u32(acc[mt][nt][2]) >> 16);
                u1.y = (unsigned short)(mono_u32(acc[mt][nt][3]) >> 16);
                *(ushort2*)&g_scores16[(size_t)r0 * M + c0]       = u0;
                *(ushort2*)&g_scores16[(size_t)(r0 + 8) * M + c0] = u1;
            }
        }
#pragma unroll
        for (int cg = 0; cg < 2; cg++) {
            float m0 = -1e30f, m1 = -1e30f;
#pragma unroll
            for (int j = 0; j < 4; j++) {
                const int nt = cg * 4 + j;
                m0 = fmaxf(m0, fmaxf(acc[mt][nt][0], acc[mt][nt][1]));
                m1 = fmaxf(m1, fmaxf(acc[mt][nt][2], acc[mt][nt][3]));
            }
            m0 = fmaxf(m0, __shfl_xor_sync(0xffffffffu, m0, 1));
            m0 = fmaxf(m0, __shfl_xor_sync(0xffffffffu, m0, 2));
            m1 = fmaxf(m1, __shfl_xor_sync(0xffffffffu, m1, 1));
            m1 = fmaxf(m1, __shfl_xor_sync(0xffffffffu, m1, 2));
            const int cbase = bn0 + wn * 64 + cg * 32;
            if ((lane & 3) == 0 && cbase < M) {
                g_cmax16[(size_t)r0 * CHKSTR + (cbase >> 5)] =
                    (unsigned short)(mono_u32(m0) >> 16);
                g_cmax16[(size_t)(r0 + 8) * CHKSTR + (cbase >> 5)] =
                    (unsigned short)(mono_u32(m1) >> 16);
            }
        }
    }
}

// ---------------- top-k candidates + exact fp32 rescore + vote ------------
#define TKTH 512
#define CANDCAP 1024

__global__ void __launch_bounds__(TKTH) topk_rescore_vote_kernel(
    const float* __restrict__ keys, const void* __restrict__ values_raw,
    float* __restrict__ out, int M, int nchunks) {
    const int b    = blockIdx.x;
    const int tid  = threadIdx.x;
    const int lane = tid & 31;
    const int w    = tid >> 5;

    __shared__ alignas(16) float xn_s[DD];     // 16B-aligned: read as float4
    __shared__ unsigned hist[4096];
    __shared__ unsigned chs[256];
    __shared__ unsigned sThr;
    __shared__ unsigned sNc, sNch;
    __shared__ int      chlist[2048];
    __shared__ int      cand_i[CANDCAP];
    __shared__ unsigned cand_u[CANDCAP];
    __shared__ float    cand_v[CANDCAP];
    __shared__ unsigned long long redK[16];
    __shared__ int      redS[16];
    __shared__ float    cls[NCLS];

    for (int i = tid; i < 4096; i += TKTH) hist[i] = 0u;
    if (tid < DD) xn_s[tid] = g_xn[(size_t)b * DD + tid];
    if (tid < NCLS) cls[tid] = 0.f;
    if (tid == 0) { sNc = 0u; sNch = 0u; }
    __syncthreads();

    const unsigned short* cmax = g_cmax16 + (size_t)b * CHKSTR;

    // phase 1: 12-bit histogram of u16 chunk maxima
    for (int i = tid; i < nchunks; i += TKTH) {
        atomicAdd(&hist[cmax[i] >> 4], 1u);
    }
    __syncthreads();

    if (tid < 256) {
        unsigned s = 0;
#pragma unroll
        for (int j = 0; j < 16; j++) s += hist[tid * 16 + j];
        chs[tid] = s;
    }
    __syncthreads();

    if (tid == 0) {
        unsigned cum = 0;
        int c = 255;
        for (; c >= 0; c--) {
            if (cum + chs[c] >= TOPK) break;
            cum += chs[c];
        }
        if (c < 0) c = 0;
        int T = c * 16;
        for (int d = c * 16 + 15; d >= c * 16; d--) {
            if (cum + hist[d] >= TOPK) { T = d; break; }
            cum += hist[d];
        }
        // lower bin edge of digit T in value space, widened by MARGIN.
        // u16 keys were formed as mono>>16, digit = key>>4 = mono>>20.
        float edge = inv_mono(((unsigned)T) << 20);
        unsigned th32 = mono_u32(edge - MARGIN);
        sThr = th32 >> 16;
    }
    __syncthreads();
    const unsigned thr = sThr;

    // phase 2: chunks whose max >= thr
    for (int i = tid; i < nchunks; i += TKTH) {
        if ((unsigned)cmax[i] >= thr) {
            unsigned p = atomicAdd(&sNch, 1u);
            if (p < 2048u) chlist[p] = i;
        }
    }
    __syncthreads();
    const int nch = (int)min(sNch, 2048u);

    // phase 3: candidate columns (coarse u16 >= thr)
    const unsigned short* row16 = g_scores16 + (size_t)b * M;
    for (int j = tid; j < nch * 32; j += TKTH) {
        const int col = chlist[j >> 5] * 32 + (j & 31);
        if (col < M && (unsigned)row16[col] >= thr) {
            unsigned p = atomicAdd(&sNc, 1u);
            if (p < (unsigned)CANDCAP) cand_i[p] = col;
        }
    }
    __syncthreads();
    const int n = (int)min(sNc, (unsigned)CANDCAP);

    // phase 4: exact fp32 rescore (warp per candidate)
    for (int j = w; j < n; j += TKTH / 32) {
        const int idx = cand_i[j];
        const float* kp = keys + (size_t)idx * DD;
        float s = 0.f;
#pragma unroll
        for (int it = 0; it < 4; it++) {
            const float4 kv = __ldg((const float4*)(kp) + lane + it * 32);
            const float4 xv = *((const float4*)xn_s + lane + it * 32);
            s += kv.x * xv.x + kv.y * xv.y + kv.z * xv.z + kv.w * xv.w;
        }
#pragma unroll
        for (int o = 16; o; o >>= 1) s += __shfl_xor_sync(0xffffffffu, s, o);
        if (lane == 0) {
            const float sv = s * g_kinv[idx];
            cand_v[j] = sv;
            cand_u[j] = mono_u32(sv);
        }
    }
    __syncthreads();

    const int is64 = g_val_is64;
    const long long* v64 = (const long long*)values_raw;
    const int*       v32 = (const int*)values_raw;

    // phase 5: exact top-50 (tie-break: score desc, index asc) + vote
    for (int it = 0; it < TOPK; it++) {
        unsigned long long best = 0ull;
        int bslot = -1;
        for (int j = tid; j < n; j += TKTH) {
            unsigned long long key =
                ((unsigned long long)cand_u[j] << 32) |
                (unsigned long long)(0xFFFFFFFFu - (unsigned)cand_i[j]);
            if (key > best) { best = key; bslot = j; }
        }
#pragma unroll
        for (int o = 16; o; o >>= 1) {
            unsigned long long ok = __shfl_xor_sync(0xffffffffu, best, o);
            int os = __shfl_xor_sync(0xffffffffu, bslot, o);
            if (ok > best) { best = ok; bslot = os; }
        }
        if (lane == 0) { redK[w] = best; redS[w] = bslot; }
        __syncthreads();
        if (tid == 0) {
            unsigned long long bb = 0ull;
            int ss2 = -1;
            for (int q = 0; q < TKTH / 32; q++)
                if (redK[q] > bb) { bb = redK[q]; ss2 = redS[q]; }
            if (ss2 >= 0) {
                int idx = cand_i[ss2];
                int lbl = is64 ? (int)v64[idx] : v32[idx];
                if (lbl >= 0 && lbl < NCLS) cls[lbl] += cand_v[ss2];
                cand_u[ss2] = 0u;
            }
        }
        __syncthreads();
    }

    if (tid < NCLS) out[b * NCLS + tid] = cls[tid];
}

// ---------------- launcher ----------------
extern "C" void kernel_launch(void* const* d_in, const int* in_sizes, int n_in,
                              void* d_out, int out_size) {
    const float* x      = (const float*)d_in[0];
    const float* keys   = (const float*)d_in[1];
    const void*  values = d_in[2];
    float*       out    = (float*)d_out;

    const int B = in_sizes[0] / DD;   // 1024
    const int M = in_sizes[2];        // 60000
    const int nchunks = (M + 31) / 32;

    norm_x_kernel<<<B, 128>>>(x);
    norm_k_kernel<<<M, 128>>>(keys);
    detect_values_kernel<<<1, 1>>>(values);

    const int dyn_smem = NSTG * STAGE_H * (int)sizeof(__nv_bfloat16); // 122880 B
    cudaFuncSetAttribute(gemm_kernel,
                         cudaFuncAttributeMaxDynamicSharedMemorySize, dyn_smem);
    dim3 grid(B / 256, (M + 127) / 128);
    gemm_kernel<<<grid, 256, dyn_smem>>>(M);

    topk_rescore_vote_kernel<<<B, TKTH>>>(keys, values, out, M, nchunks);
}